// round 1
// baseline (speedup 1.0000x reference)
#include <cuda_runtime.h>
#include <math.h>

#define BATCH   4
#define QL      1024
#define KVL     4096
#define DIMC    256
#define NHEADS  8
#define HDIM    32

// ---------------- scratch (device globals; no runtime allocation) ----------------
__device__ float g_Q[BATCH * NHEADS * QL * HDIM];    //  4 MB, scaled Q
__device__ float g_K[BATCH * NHEADS * KVL * HDIM];   // 16 MB
__device__ float g_V[BATCH * NHEADS * KVL * HDIM];   // 16 MB
__device__ float g_X[BATCH * QL * DIMC];             //  4 MB, attention output

// ---------------- generic tiled GEMM:  C[m,n] = sum_k A[m,k]*W[n,k] + bias[n] ----
// MODE 0: Q projection  -> g_Q[((b*8+h)*QL + qm)*32 + d] * scale
// MODE 1: KV projection -> g_K / g_V  [((b*8+h)*KVL + km)*32 + d]
// MODE 2: out projection-> out[m*256+n]   (A is read from g_X)
template <int MODE>
__global__ __launch_bounds__(256)
void gemm_proj(const float* __restrict__ A, const float* __restrict__ W,
               const float* __restrict__ bias, float* __restrict__ out,
               int M, int N, int K)
{
    __shared__ __align__(16) float As[16][128];
    __shared__ __align__(16) float Ws[16][64];

    const float* Aptr = (MODE == 2) ? (const float*)g_X : A;

    const int m0 = blockIdx.x * 128;
    const int n0 = blockIdx.y * 64;
    const int tid = threadIdx.x;

    const int rm = (tid / 16) * 8;   // 0..120
    const int rn = (tid % 16) * 4;   // 0..60

    float acc[8][4];
#pragma unroll
    for (int i = 0; i < 8; i++)
#pragma unroll
        for (int j = 0; j < 4; j++) acc[i][j] = 0.f;

    for (int k0 = 0; k0 < K; k0 += 16) {
        // load A tile 128x16 (512 float4), store transposed As[k][m]
#pragma unroll
        for (int i = 0; i < 2; i++) {
            int f = tid + i * 256;            // 0..511
            int am = f & 127;
            int kc = f >> 7;                  // 0..3
            float4 v = *(const float4*)&Aptr[(size_t)(m0 + am) * K + k0 + kc * 4];
            As[kc * 4 + 0][am] = v.x;
            As[kc * 4 + 1][am] = v.y;
            As[kc * 4 + 2][am] = v.z;
            As[kc * 4 + 3][am] = v.w;
        }
        // load W tile 64x16 (256 float4), store transposed Ws[k][n]
        {
            int wn = tid & 63;
            int kc = tid >> 6;                // 0..3
            float4 v = *(const float4*)&W[(size_t)(n0 + wn) * K + k0 + kc * 4];
            Ws[kc * 4 + 0][wn] = v.x;
            Ws[kc * 4 + 1][wn] = v.y;
            Ws[kc * 4 + 2][wn] = v.z;
            Ws[kc * 4 + 3][wn] = v.w;
        }
        __syncthreads();

#pragma unroll
        for (int kk = 0; kk < 16; kk++) {
            float a[8], w[4];
            *(float4*)&a[0] = *(float4*)&As[kk][rm];
            *(float4*)&a[4] = *(float4*)&As[kk][rm + 4];
            *(float4*)&w[0] = *(float4*)&Ws[kk][rn];
#pragma unroll
            for (int i = 0; i < 8; i++)
#pragma unroll
                for (int j = 0; j < 4; j++)
                    acc[i][j] += a[i] * w[j];
        }
        __syncthreads();
    }

    const float scale = 0.17677669529663687f;  // hd^-0.5

#pragma unroll
    for (int i = 0; i < 8; i++) {
        int m = m0 + rm + i;
#pragma unroll
        for (int j = 0; j < 4; j++) {
            int n = n0 + rn + j;
            float val = acc[i][j] + bias[n];
            if (MODE == 0) {
                int b = m >> 10, qm = m & 1023;
                int h = n >> 5, d = n & 31;
                g_Q[(((size_t)(b * 8 + h) * QL) + qm) * HDIM + d] = val * scale;
            } else if (MODE == 1) {
                int b = m >> 12, km = m & 4095;
                if (n < 256) {
                    int h = n >> 5, d = n & 31;
                    g_K[(((size_t)(b * 8 + h) * KVL) + km) * HDIM + d] = val;
                } else {
                    int n2 = n - 256;
                    int h = n2 >> 5, d = n2 & 31;
                    g_V[(((size_t)(b * 8 + h) * KVL) + km) * HDIM + d] = val;
                }
            } else {
                out[(size_t)m * 256 + n] = val;
            }
        }
    }
}

// ---------------- fused flash attention with relative-position bias ----------------
// grid: (qtile=16, h=8, b=4), block: 256 threads = 8 warps
// warp w: rows (w&1)*32 + lane ; k-chunk (w>>1)*16 ; j-chunk (w>>1)*8
__global__ __launch_bounds__(256)
void attn_kernel(const float* __restrict__ bias_table, const int* __restrict__ rel_index)
{
    __shared__ __align__(16) float Ksm[64][36];
    __shared__ __align__(16) float Vsm[64][36];
    __shared__ __align__(16) float PU[64 * 68];     // union: int rel[64][64] / float P[64][68]
    __shared__ float sm_m[64], sm_l[64], sm_alpha[64];
    __shared__ float sm_part[64][4];

    const int qt = blockIdx.x, h = blockIdx.y, b = blockIdx.z;
    const int tid = threadIdx.x;
    const int w = tid >> 5, lane = tid & 31;
    const int row = ((w & 1) << 5) + lane;   // 0..63 (q row within tile)
    const int chunk = w >> 1;                // 0..3
    const int kc0 = chunk * 16;
    const int j0 = chunk * 8;

    int* relsm = (int*)PU;

    // load my Q row into registers (already scaled)
    float qreg[32];
    {
        const float* qptr = g_Q + (((size_t)(b * 8 + h) * QL) + qt * 64 + row) * HDIM;
#pragma unroll
        for (int i = 0; i < 8; i++)
            *(float4*)&qreg[i * 4] = *(const float4*)&qptr[i * 4];
    }

    float O[8];
#pragma unroll
    for (int j = 0; j < 8; j++) O[j] = 0.f;

    if (tid < 64) { sm_m[tid] = -1e30f; sm_l[tid] = 0.f; }

    const float* kbase = g_K + ((size_t)(b * 8 + h) * KVL) * HDIM;
    const float* vbase = g_V + ((size_t)(b * 8 + h) * KVL) * HDIM;
    const int* rbase = rel_index + (size_t)(qt * 64) * KVL;

    for (int kt = 0; kt < KVL / 64; kt++) {
        __syncthreads();   // previous tile's PV / stats done; smem reusable

        // ---- load K, V tiles (64x32 each, float4) ----
        const float* kb = kbase + (size_t)(kt * 64) * HDIM;
        const float* vb = vbase + (size_t)(kt * 64) * HDIM;
#pragma unroll
        for (int i = 0; i < 2; i++) {
            int f = tid + i * 256;       // 0..511
            int r = f >> 3;
            int dc = (f & 7) << 2;
            *(float4*)&Ksm[r][dc] = *(const float4*)&kb[r * HDIM + dc];
            *(float4*)&Vsm[r][dc] = *(const float4*)&vb[r * HDIM + dc];
        }
        // ---- load rel_index tile (64x64 int, int4) ----
        const int* rb = rbase + kt * 64;
#pragma unroll
        for (int i = 0; i < 4; i++) {
            int f = tid + i * 256;       // 0..1023
            int r = f >> 4;
            int c = (f & 15) << 2;
            *(int4*)&relsm[r * 64 + c] = *(const int4*)&rb[(size_t)r * KVL + c];
        }
        __syncthreads();

        // ---- S = Q.K^T + bias : each thread 1 row x 16 k-cols ----
        float s[16];
        float smax = -1e30f;
#pragma unroll
        for (int i = 0; i < 16; i++) {
            int kc = kc0 + i;
            int ridx = relsm[row * 64 + kc];
            float acc = __ldg(&bias_table[(size_t)ridx * NHEADS + h]);
#pragma unroll
            for (int d4 = 0; d4 < 8; d4++) {
                float4 kv = *(const float4*)&Ksm[kc][d4 * 4];   // warp-uniform -> broadcast
                acc += qreg[d4 * 4 + 0] * kv.x;
                acc += qreg[d4 * 4 + 1] * kv.y;
                acc += qreg[d4 * 4 + 2] * kv.z;
                acc += qreg[d4 * 4 + 3] * kv.w;
            }
            s[i] = acc;
            smax = fmaxf(smax, acc);
        }
        sm_part[row][chunk] = smax;
        __syncthreads();

        // ---- online max update (64 row threads) ----
        if (tid < 64) {
            float mt = fmaxf(fmaxf(sm_part[tid][0], sm_part[tid][1]),
                             fmaxf(sm_part[tid][2], sm_part[tid][3]));
            float mo = sm_m[tid];
            float mn = fmaxf(mo, mt);
            sm_m[tid] = mn;
            sm_alpha[tid] = __expf(mo - mn);
        }
        __syncthreads();

        // ---- P = exp(S - m), write P to smem, partial row sums, rescale O ----
        const float mrow = sm_m[row];
        const float a = sm_alpha[row];
        float lsum = 0.f;
#pragma unroll
        for (int i4 = 0; i4 < 4; i4++) {
            float4 p4;
            p4.x = __expf(s[i4 * 4 + 0] - mrow);
            p4.y = __expf(s[i4 * 4 + 1] - mrow);
            p4.z = __expf(s[i4 * 4 + 2] - mrow);
            p4.w = __expf(s[i4 * 4 + 3] - mrow);
            lsum += p4.x + p4.y + p4.z + p4.w;
            *(float4*)&PU[row * 68 + kc0 + i4 * 4] = p4;
        }
        sm_part[row][chunk] = lsum;
#pragma unroll
        for (int j = 0; j < 8; j++) O[j] *= a;
        __syncthreads();

        if (tid < 64) {
            sm_l[tid] = sm_l[tid] * sm_alpha[tid] +
                        sm_part[tid][0] + sm_part[tid][1] + sm_part[tid][2] + sm_part[tid][3];
        }

        // ---- O += P @ V : thread = 1 row x 8 head-dims ----
#pragma unroll
        for (int k4 = 0; k4 < 64; k4 += 4) {
            float4 p4 = *(const float4*)&PU[row * 68 + k4];
#pragma unroll
            for (int i = 0; i < 4; i++) {
                float p = (i == 0) ? p4.x : (i == 1) ? p4.y : (i == 2) ? p4.z : p4.w;
                float4 v0 = *(const float4*)&Vsm[k4 + i][j0];       // warp-uniform
                float4 v1 = *(const float4*)&Vsm[k4 + i][j0 + 4];
                O[0] += p * v0.x; O[1] += p * v0.y; O[2] += p * v0.z; O[3] += p * v0.w;
                O[4] += p * v1.x; O[5] += p * v1.y; O[6] += p * v1.z; O[7] += p * v1.w;
            }
        }
    }
    __syncthreads();

    const float linv = 1.f / sm_l[row];
    float* xp = g_X + ((size_t)(b * QL) + qt * 64 + row) * DIMC + h * HDIM + j0;
    float4 o0, o1;
    o0.x = O[0] * linv; o0.y = O[1] * linv; o0.z = O[2] * linv; o0.w = O[3] * linv;
    o1.x = O[4] * linv; o1.y = O[5] * linv; o1.z = O[6] * linv; o1.w = O[7] * linv;
    *(float4*)&xp[0] = o0;
    *(float4*)&xp[4] = o1;
}

// ---------------- launch ----------------
extern "C" void kernel_launch(void* const* d_in, const int* in_sizes, int n_in,
                              void* d_out, int out_size)
{
    const float* q          = (const float*)d_in[0];
    const float* kv         = (const float*)d_in[1];
    const float* Wq         = (const float*)d_in[2];
    const float* bq         = (const float*)d_in[3];
    const float* Wkv        = (const float*)d_in[4];
    const float* bkv        = (const float*)d_in[5];
    const float* bias_table = (const float*)d_in[6];
    const float* Wp         = (const float*)d_in[7];
    const float* bp         = (const float*)d_in[8];
    const int*   rel_index  = (const int*)d_in[9];
    float* out = (float*)d_out;

    // Q projection: M=4096, N=256, K=256
    gemm_proj<0><<<dim3(32, 4), 256>>>(q, Wq, bq, nullptr, BATCH * QL, DIMC, DIMC);
    // KV projection: M=16384, N=512, K=256
    gemm_proj<1><<<dim3(128, 8), 256>>>(kv, Wkv, bkv, nullptr, BATCH * KVL, 2 * DIMC, DIMC);
    // fused attention
    attn_kernel<<<dim3(16, 8, 4), 256>>>(bias_table, rel_index);
    // output projection: M=4096, N=256, K=256
    gemm_proj<2><<<dim3(32, 4), 256>>>(nullptr, Wp, bp, out, BATCH * QL, DIMC, DIMC);
}

// round 6
// speedup vs baseline: 2.0327x; 2.0327x over previous
#include <cuda_runtime.h>
#include <stdint.h>
#include <math.h>

#define BATCH   4
#define QL      1024
#define KVL     4096
#define DIMC    256
#define NHEADS  8
#define HDIM    32

// ---------------- scratch (device globals; no runtime allocation) ----------------
__device__ float g_Q[BATCH * NHEADS * QL * HDIM];    //  4 MB, scaled Q
__device__ float g_K[BATCH * NHEADS * KVL * HDIM];   // 16 MB
__device__ float g_V[BATCH * NHEADS * KVL * HDIM];   // 16 MB
__device__ float g_X[BATCH * QL * DIMC];             //  4 MB, attention output

// ---------------- generic tiled GEMM:  C[m,n] = sum_k A[m,k]*W[n,k] + bias[n] ----
template <int MODE>
__global__ __launch_bounds__(256)
void gemm_proj(const float* __restrict__ A, const float* __restrict__ W,
               const float* __restrict__ bias, float* __restrict__ out,
               int M, int N, int K)
{
    __shared__ __align__(16) float As[16][128];
    __shared__ __align__(16) float Ws[16][64];

    const float* Aptr = (MODE == 2) ? (const float*)g_X : A;

    const int m0 = blockIdx.x * 128;
    const int n0 = blockIdx.y * 64;
    const int tid = threadIdx.x;

    const int rm = (tid / 16) * 8;
    const int rn = (tid % 16) * 4;

    float acc[8][4];
#pragma unroll
    for (int i = 0; i < 8; i++)
#pragma unroll
        for (int j = 0; j < 4; j++) acc[i][j] = 0.f;

    for (int k0 = 0; k0 < K; k0 += 16) {
#pragma unroll
        for (int i = 0; i < 2; i++) {
            int f = tid + i * 256;
            int am = f & 127;
            int kc = f >> 7;
            float4 v = *(const float4*)&Aptr[(size_t)(m0 + am) * K + k0 + kc * 4];
            As[kc * 4 + 0][am] = v.x;
            As[kc * 4 + 1][am] = v.y;
            As[kc * 4 + 2][am] = v.z;
            As[kc * 4 + 3][am] = v.w;
        }
        {
            int wn = tid & 63;
            int kc = tid >> 6;
            float4 v = *(const float4*)&W[(size_t)(n0 + wn) * K + k0 + kc * 4];
            Ws[kc * 4 + 0][wn] = v.x;
            Ws[kc * 4 + 1][wn] = v.y;
            Ws[kc * 4 + 2][wn] = v.z;
            Ws[kc * 4 + 3][wn] = v.w;
        }
        __syncthreads();

#pragma unroll
        for (int kk = 0; kk < 16; kk++) {
            float a[8], w[4];
            *(float4*)&a[0] = *(float4*)&As[kk][rm];
            *(float4*)&a[4] = *(float4*)&As[kk][rm + 4];
            *(float4*)&w[0] = *(float4*)&Ws[kk][rn];
#pragma unroll
            for (int i = 0; i < 8; i++)
#pragma unroll
                for (int j = 0; j < 4; j++)
                    acc[i][j] += a[i] * w[j];
        }
        __syncthreads();
    }

    const float scale = 0.17677669529663687f;

#pragma unroll
    for (int i = 0; i < 8; i++) {
        int m = m0 + rm + i;
#pragma unroll
        for (int j = 0; j < 4; j++) {
            int n = n0 + rn + j;
            float val = acc[i][j] + bias[n];
            if (MODE == 0) {
                int b = m >> 10, qm = m & 1023;
                int h = n >> 5, d = n & 31;
                g_Q[(((size_t)(b * 8 + h) * QL) + qm) * HDIM + d] = val * scale;
            } else if (MODE == 1) {
                int b = m >> 12, km = m & 4095;
                if (n < 256) {
                    int h = n >> 5, d = n & 31;
                    g_K[(((size_t)(b * 8 + h) * KVL) + km) * HDIM + d] = val;
                } else {
                    int n2 = n - 256;
                    int h = n2 >> 5, d = n2 & 31;
                    g_V[(((size_t)(b * 8 + h) * KVL) + km) * HDIM + d] = val;
                }
            } else {
                out[(size_t)m * 256 + n] = val;
            }
        }
    }
}

// ============================================================================
// tf32 tensor-core fused flash attention; bias taken DIRECTLY from
// bias_table[rel_index[q][k]*8 + h].
// grid (qt=8 [128 q-rows], h=8, b=4), block 256 = 8 warps.
// Each warp owns 16 q-rows (m16); softmax state in registers.
// ============================================================================

__device__ __forceinline__ float tf32r(float x) {
    uint32_t u;
    asm("cvt.rna.tf32.f32 %0, %1;" : "=r"(u) : "f"(x));
    return __uint_as_float(u);
}

__device__ __forceinline__ void mma_tf32(float c[4],
                                         uint32_t a0, uint32_t a1, uint32_t a2, uint32_t a3,
                                         uint32_t b0, uint32_t b1) {
    asm volatile(
        "mma.sync.aligned.m16n8k8.row.col.f32.tf32.tf32.f32 "
        "{%0,%1,%2,%3},{%4,%5,%6,%7},{%8,%9},{%0,%1,%2,%3};"
        : "+f"(c[0]), "+f"(c[1]), "+f"(c[2]), "+f"(c[3])
        : "r"(a0), "r"(a1), "r"(a2), "r"(a3), "r"(b0), "r"(b1));
}

// smem layout (floats)
#define KSM_OFF 0
#define VSM_OFF 2304            // 64*36
#define PSM_OFF 4608            // + 64*36
#define ATTN_SMEM_FLOATS 13312  // + 128*68
#define ATTN_SMEM_BYTES (ATTN_SMEM_FLOATS * 4)

__global__ __launch_bounds__(256)
void attn_tc(const float* __restrict__ bias_table, const int* __restrict__ rel_index)
{
    extern __shared__ __align__(16) float smem[];
    float* Ksm  = smem + KSM_OFF;   // [64][36]
    float* Vsm  = smem + VSM_OFF;   // [64][36]
    float* Psm  = smem + PSM_OFF;   // [128][68]

    const int qt = blockIdx.x, h = blockIdx.y, b = blockIdx.z;
    const int tid = threadIdx.x;
    const int w = tid >> 5, lane = tid & 31;
    const int g = lane >> 2, tig = lane & 3;
    const int r0 = w * 16 + g;          // q-row in tile (0..127)
    const int r1 = r0 + 8;

    // ---- Q fragments (registers, fixed for whole kernel) ----
    uint32_t qa[4][4];
    {
        const float* qbase = g_Q + (((size_t)(b * 8 + h) * QL) + qt * 128) * HDIM;
#pragma unroll
        for (int ks = 0; ks < 4; ks++) {
            qa[ks][0] = __float_as_uint(tf32r(qbase[(size_t)r0 * HDIM + ks * 8 + tig]));
            qa[ks][1] = __float_as_uint(tf32r(qbase[(size_t)r1 * HDIM + ks * 8 + tig]));
            qa[ks][2] = __float_as_uint(tf32r(qbase[(size_t)r0 * HDIM + ks * 8 + tig + 4]));
            qa[ks][3] = __float_as_uint(tf32r(qbase[(size_t)r1 * HDIM + ks * 8 + tig + 4]));
        }
    }

    float o[4][4];
#pragma unroll
    for (int i = 0; i < 4; i++)
#pragma unroll
        for (int j = 0; j < 4; j++) o[i][j] = 0.f;

    float m0 = -1e30f, m1 = -1e30f, l0 = 0.f, l1 = 0.f;

    const float* kbase = g_K + ((size_t)(b * 8 + h) * KVL) * HDIM;
    const float* vbase = g_V + ((size_t)(b * 8 + h) * KVL) * HDIM;
    // rel_index rows for this thread's two fragment rows
    const int* rel0 = rel_index + (size_t)(qt * 128 + r0) * KVL;
    const int* rel1 = rel_index + (size_t)(qt * 128 + r1) * KVL;

    for (int kt = 0; kt < KVL / 64; kt++) {
        __syncthreads();   // prev tile done with Ksm/Vsm

        // ---- load K,V tiles (64x32 each, FULL tile: 512 float4s over 2 iters) ----
#pragma unroll
        for (int i = 0; i < 2; i++) {
            int f = tid + i * 256;           // 0..511
            int r = f >> 3;                  // 0..63
            int c4 = (f & 7) << 2;           // 0..28
            float4 kv4 = *(const float4*)&kbase[((size_t)(kt * 64) + r) * HDIM + c4];
            Ksm[r * 36 + c4 + 0] = tf32r(kv4.x);
            Ksm[r * 36 + c4 + 1] = tf32r(kv4.y);
            Ksm[r * 36 + c4 + 2] = tf32r(kv4.z);
            Ksm[r * 36 + c4 + 3] = tf32r(kv4.w);
            float4 vv4 = *(const float4*)&vbase[((size_t)(kt * 64) + r) * HDIM + c4];
            Vsm[r * 36 + c4 + 0] = tf32r(vv4.x);
            Vsm[r * 36 + c4 + 1] = tf32r(vv4.y);
            Vsm[r * 36 + c4 + 2] = tf32r(vv4.z);
            Vsm[r * 36 + c4 + 3] = tf32r(vv4.w);
        }
        __syncthreads();

        // ---- S = Q K^T + bias (bias gathered straight from rel_index) ----
        float sA[8][4];
#pragma unroll
        for (int nt = 0; nt < 8; nt++) {
            const int cc = kt * 64 + nt * 8 + tig * 2;
            int2 ia = __ldg((const int2*)&rel0[cc]);
            int2 ib = __ldg((const int2*)&rel1[cc]);
            sA[nt][0] = __ldg(&bias_table[(size_t)ia.x * NHEADS + h]);
            sA[nt][1] = __ldg(&bias_table[(size_t)ia.y * NHEADS + h]);
            sA[nt][2] = __ldg(&bias_table[(size_t)ib.x * NHEADS + h]);
            sA[nt][3] = __ldg(&bias_table[(size_t)ib.y * NHEADS + h]);
#pragma unroll
            for (int ks = 0; ks < 4; ks++) {
                uint32_t b0 = __float_as_uint(Ksm[(nt * 8 + g) * 36 + ks * 8 + tig]);
                uint32_t b1 = __float_as_uint(Ksm[(nt * 8 + g) * 36 + ks * 8 + tig + 4]);
                mma_tf32(sA[nt], qa[ks][0], qa[ks][1], qa[ks][2], qa[ks][3], b0, b1);
            }
        }

        // ---- online softmax (register state; reduce over tig quad) ----
        float mloc0 = -1e30f, mloc1 = -1e30f;
#pragma unroll
        for (int nt = 0; nt < 8; nt++) {
            mloc0 = fmaxf(mloc0, fmaxf(sA[nt][0], sA[nt][1]));
            mloc1 = fmaxf(mloc1, fmaxf(sA[nt][2], sA[nt][3]));
        }
        mloc0 = fmaxf(mloc0, __shfl_xor_sync(0xffffffffu, mloc0, 1));
        mloc0 = fmaxf(mloc0, __shfl_xor_sync(0xffffffffu, mloc0, 2));
        mloc1 = fmaxf(mloc1, __shfl_xor_sync(0xffffffffu, mloc1, 1));
        mloc1 = fmaxf(mloc1, __shfl_xor_sync(0xffffffffu, mloc1, 2));

        float nm0 = fmaxf(m0, mloc0);
        float nm1 = fmaxf(m1, mloc1);
        float a0 = __expf(m0 - nm0);
        float a1 = __expf(m1 - nm1);
        m0 = nm0; m1 = nm1;

        float lsum0 = 0.f, lsum1 = 0.f;
#pragma unroll
        for (int nt = 0; nt < 8; nt++) {
            float p0 = __expf(sA[nt][0] - m0);
            float p1 = __expf(sA[nt][1] - m0);
            float p2 = __expf(sA[nt][2] - m1);
            float p3 = __expf(sA[nt][3] - m1);
            lsum0 += p0 + p1;
            lsum1 += p2 + p3;
            int cc = nt * 8 + tig * 2;
            float2 w0; w0.x = tf32r(p0); w0.y = tf32r(p1);
            float2 w1; w1.x = tf32r(p2); w1.y = tf32r(p3);
            *(float2*)&Psm[r0 * 68 + cc] = w0;
            *(float2*)&Psm[r1 * 68 + cc] = w1;
        }
        lsum0 += __shfl_xor_sync(0xffffffffu, lsum0, 1);
        lsum0 += __shfl_xor_sync(0xffffffffu, lsum0, 2);
        lsum1 += __shfl_xor_sync(0xffffffffu, lsum1, 1);
        lsum1 += __shfl_xor_sync(0xffffffffu, lsum1, 2);
        l0 = l0 * a0 + lsum0;
        l1 = l1 * a1 + lsum1;

#pragma unroll
        for (int nt2 = 0; nt2 < 4; nt2++) {
            o[nt2][0] *= a0; o[nt2][1] *= a0;
            o[nt2][2] *= a1; o[nt2][3] *= a1;
        }
        __syncwarp();  // P visible within warp (warp-local rows)

        // ---- O += P V (tensor core) ----
#pragma unroll
        for (int kc = 0; kc < 8; kc++) {
            uint32_t a0r = __float_as_uint(Psm[r0 * 68 + kc * 8 + tig]);
            uint32_t a1r = __float_as_uint(Psm[r1 * 68 + kc * 8 + tig]);
            uint32_t a2r = __float_as_uint(Psm[r0 * 68 + kc * 8 + tig + 4]);
            uint32_t a3r = __float_as_uint(Psm[r1 * 68 + kc * 8 + tig + 4]);
#pragma unroll
            for (int nt2 = 0; nt2 < 4; nt2++) {
                uint32_t b0 = __float_as_uint(Vsm[(kc * 8 + tig) * 36 + nt2 * 8 + g]);
                uint32_t b1 = __float_as_uint(Vsm[(kc * 8 + tig + 4) * 36 + nt2 * 8 + g]);
                mma_tf32(o[nt2], a0r, a1r, a2r, a3r, b0, b1);
            }
        }
        __syncwarp();  // PV reads done before next tile's P stores
    }

    // ---- epilogue: normalize + write to g_X ----
    float linv0 = 1.f / l0;
    float linv1 = 1.f / l1;
    float* xb = g_X + ((size_t)b * QL + qt * 128) * DIMC + h * HDIM;
#pragma unroll
    for (int nt2 = 0; nt2 < 4; nt2++) {
        int cc = nt2 * 8 + tig * 2;
        float2 v0; v0.x = o[nt2][0] * linv0; v0.y = o[nt2][1] * linv0;
        float2 v1; v1.x = o[nt2][2] * linv1; v1.y = o[nt2][3] * linv1;
        *(float2*)&xb[(size_t)r0 * DIMC + cc] = v0;
        *(float2*)&xb[(size_t)r1 * DIMC + cc] = v1;
    }
}

// ---------------- launch ----------------
extern "C" void kernel_launch(void* const* d_in, const int* in_sizes, int n_in,
                              void* d_out, int out_size)
{
    const float* q          = (const float*)d_in[0];
    const float* kv         = (const float*)d_in[1];
    const float* Wq         = (const float*)d_in[2];
    const float* bq         = (const float*)d_in[3];
    const float* Wkv        = (const float*)d_in[4];
    const float* bkv        = (const float*)d_in[5];
    const float* bias_table = (const float*)d_in[6];
    const float* Wp         = (const float*)d_in[7];
    const float* bp         = (const float*)d_in[8];
    const int*   rel_index  = (const int*)d_in[9];
    float* out = (float*)d_out;

    cudaFuncSetAttribute(attn_tc, cudaFuncAttributeMaxDynamicSharedMemorySize,
                         ATTN_SMEM_BYTES);

    gemm_proj<0><<<dim3(32, 4), 256>>>(q, Wq, bq, nullptr, BATCH * QL, DIMC, DIMC);
    gemm_proj<1><<<dim3(128, 8), 256>>>(kv, Wkv, bkv, nullptr, BATCH * KVL, 2 * DIMC, DIMC);
    attn_tc<<<dim3(8, 8, 4), 256, ATTN_SMEM_BYTES>>>(bias_table, rel_index);
    gemm_proj<2><<<dim3(32, 4), 256>>>(nullptr, Wp, bp, out, BATCH * QL, DIMC, DIMC);
}

// round 7
// speedup vs baseline: 2.5734x; 1.2660x over previous
#include <cuda_runtime.h>
#include <stdint.h>
#include <math.h>

#define BATCH   4
#define QL      1024
#define KVL     4096
#define DIMC    256
#define NHEADS  8
#define HDIM    32

// ---------------- scratch (device globals; no runtime allocation) ----------------
__device__ float g_Q[BATCH * NHEADS * QL * HDIM];    //  4 MB, scaled Q
__device__ float g_K[BATCH * NHEADS * KVL * HDIM];   // 16 MB
__device__ float g_V[BATCH * NHEADS * KVL * HDIM];   // 16 MB
__device__ float g_X[BATCH * QL * DIMC];             //  4 MB, attention output

// ---------------- common helpers ----------------
__device__ __forceinline__ float tf32r(float x) {
    uint32_t u;
    asm("cvt.rna.tf32.f32 %0, %1;" : "=r"(u) : "f"(x));
    return __uint_as_float(u);
}

__device__ __forceinline__ void mma_tf32(float c[4],
                                         uint32_t a0, uint32_t a1, uint32_t a2, uint32_t a3,
                                         uint32_t b0, uint32_t b1) {
    asm volatile(
        "mma.sync.aligned.m16n8k8.row.col.f32.tf32.tf32.f32 "
        "{%0,%1,%2,%3},{%4,%5,%6,%7},{%8,%9},{%0,%1,%2,%3};"
        : "+f"(c[0]), "+f"(c[1]), "+f"(c[2]), "+f"(c[3])
        : "r"(a0), "r"(a1), "r"(a2), "r"(a3), "r"(b0), "r"(b1));
}

__device__ __forceinline__ void cpa16(void* dst, const void* src) {
    uint32_t d = (uint32_t)__cvta_generic_to_shared(dst);
    asm volatile("cp.async.cg.shared.global [%0], [%1], 16;\n" :: "r"(d), "l"(src));
}
__device__ __forceinline__ void cp_commit() { asm volatile("cp.async.commit_group;\n"); }
template<int N> __device__ __forceinline__ void cp_wait() {
    asm volatile("cp.async.wait_group %0;\n" :: "n"(N));
}

// ============================================================================
// tf32 tensor-core projection GEMM:  C[m,n] = sum_k A[m,k]*W[n,k] + bias[n]
// Tile 128(M) x 64(N), K=256 in 8 chunks of 32, cp.async double buffered.
// Block 256 thr = 8 warps in 4x2 grid; warp tile 32x32 (2 m-frags x 4 n-frags).
// ============================================================================
#define GBUF 6912   // floats per buffer: A[128][36] (4608) + W[64][36] (2304)
#define GEMM_SMEM_BYTES (2 * GBUF * 4)

template<int MODE>   // 0: Q proj, 1: KV proj, 2: out proj
__global__ __launch_bounds__(256)
void gemm_tc(const float* __restrict__ A_, const float* __restrict__ W,
             const float* __restrict__ bias, float* __restrict__ out)
{
    extern __shared__ __align__(16) float sm[];
    const float* A = (MODE == 2) ? (const float*)g_X : A_;

    const int m0 = blockIdx.x * 128, n0 = blockIdx.y * 64;
    const int tid = threadIdx.x, w = tid >> 5, lane = tid & 31;
    const int g = lane >> 2, tig = lane & 3;
    const int wy = w >> 1, wx = w & 1;

    float acc[2][4][4];
#pragma unroll
    for (int i = 0; i < 2; i++)
#pragma unroll
        for (int j = 0; j < 4; j++)
#pragma unroll
            for (int q = 0; q < 4; q++) acc[i][j][q] = 0.f;

    // issue cp.async loads for chunk k0 into buffer buf
    auto issue = [&](int buf, int k0) {
        float* As = sm + buf * GBUF;
        float* Ws = As + 4608;
#pragma unroll
        for (int i = 0; i < 4; i++) {
            int f = tid + i * 256;           // 0..1023 : 128 rows x 8 float4
            int r = f >> 3, c4 = (f & 7) << 2;
            cpa16(&As[r * 36 + c4], &A[(size_t)(m0 + r) * DIMC + k0 + c4]);
        }
#pragma unroll
        for (int i = 0; i < 2; i++) {
            int f = tid + i * 256;           // 0..511 : 64 rows x 8 float4
            int r = f >> 3, c4 = (f & 7) << 2;
            cpa16(&Ws[r * 36 + c4], &W[(size_t)(n0 + r) * DIMC + k0 + c4]);
        }
    };

    issue(0, 0); cp_commit();

    for (int c = 0; c < 8; c++) {
        __syncthreads();                       // all warps done with buffer being refilled
        if (c < 7) { issue((c + 1) & 1, (c + 1) * 32); cp_commit(); }
        if (c < 7) cp_wait<1>(); else cp_wait<0>();
        __syncthreads();                       // chunk c visible to all

        const float* As = sm + (c & 1) * GBUF;
        const float* Ws = As + 4608;
#pragma unroll
        for (int ks = 0; ks < 4; ks++) {
            uint32_t a[2][4];
#pragma unroll
            for (int mf = 0; mf < 2; mf++) {
                int R = wy * 32 + mf * 16;
                a[mf][0] = __float_as_uint(tf32r(As[(R + g) * 36 + ks * 8 + tig]));
                a[mf][1] = __float_as_uint(tf32r(As[(R + g + 8) * 36 + ks * 8 + tig]));
                a[mf][2] = __float_as_uint(tf32r(As[(R + g) * 36 + ks * 8 + tig + 4]));
                a[mf][3] = __float_as_uint(tf32r(As[(R + g + 8) * 36 + ks * 8 + tig + 4]));
            }
#pragma unroll
            for (int nf = 0; nf < 4; nf++) {
                int Nr = wx * 32 + nf * 8;
                uint32_t b0 = __float_as_uint(tf32r(Ws[(Nr + g) * 36 + ks * 8 + tig]));
                uint32_t b1 = __float_as_uint(tf32r(Ws[(Nr + g) * 36 + ks * 8 + tig + 4]));
#pragma unroll
                for (int mf = 0; mf < 2; mf++)
                    mma_tf32(acc[mf][nf], a[mf][0], a[mf][1], a[mf][2], a[mf][3], b0, b1);
            }
        }
    }

    // ---- epilogue ----
    const float scale = 0.17677669529663687f;
#pragma unroll
    for (int mf = 0; mf < 2; mf++) {
#pragma unroll
        for (int nf = 0; nf < 4; nf++) {
#pragma unroll
            for (int half = 0; half < 2; half++) {
                int m = m0 + wy * 32 + mf * 16 + g + half * 8;
                int n = n0 + wx * 32 + nf * 8 + tig * 2;
                float v0 = acc[mf][nf][half * 2 + 0] + bias[n];
                float v1 = acc[mf][nf][half * 2 + 1] + bias[n + 1];
                if (MODE == 0) {
                    int b = m >> 10, qm = m & 1023;
                    int h = n >> 5, d = n & 31;
                    float2 v; v.x = v0 * scale; v.y = v1 * scale;
                    *(float2*)&g_Q[(((size_t)(b * 8 + h) * QL) + qm) * HDIM + d] = v;
                } else if (MODE == 1) {
                    int b = m >> 12, km = m & 4095;
                    float2 v; v.x = v0; v.y = v1;
                    if (n < 256) {
                        int h = n >> 5, d = n & 31;
                        *(float2*)&g_K[(((size_t)(b * 8 + h) * KVL) + km) * HDIM + d] = v;
                    } else {
                        int n2 = n - 256;
                        int h = n2 >> 5, d = n2 & 31;
                        *(float2*)&g_V[(((size_t)(b * 8 + h) * KVL) + km) * HDIM + d] = v;
                    }
                } else {
                    float2 v; v.x = v0; v.y = v1;
                    *(float2*)&out[(size_t)m * 256 + n] = v;
                }
            }
        }
    }
}

// ============================================================================
// tf32 tensor-core fused flash attention, cp.async double-buffered K/V.
// bias taken directly from bias_table[rel_index[q][k]*8 + h].
// grid (qt=8 [128 q-rows], h=8, b=4), block 256 = 8 warps.
// ============================================================================
// smem floats: buf0 K[64][36]+V[64][36] (4608), buf1 (4608), Psm 128*68 (8704)
#define KVBUF 4608
#define PSM_OFF 9216
#define ATTN_SMEM_FLOATS (9216 + 8704)
#define ATTN_SMEM_BYTES (ATTN_SMEM_FLOATS * 4)

__global__ __launch_bounds__(256)
void attn_tc(const float* __restrict__ bias_table, const int* __restrict__ rel_index)
{
    extern __shared__ __align__(16) float smem[];
    float* Psm = smem + PSM_OFF;    // [128][68]

    const int qt = blockIdx.x, h = blockIdx.y, b = blockIdx.z;
    const int tid = threadIdx.x;
    const int w = tid >> 5, lane = tid & 31;
    const int g = lane >> 2, tig = lane & 3;
    const int r0 = w * 16 + g;          // q-row in tile (0..127)
    const int r1 = r0 + 8;

    const float* kbase = g_K + ((size_t)(b * 8 + h) * KVL) * HDIM;
    const float* vbase = g_V + ((size_t)(b * 8 + h) * KVL) * HDIM;
    const int* rel0 = rel_index + (size_t)(qt * 128 + r0) * KVL;
    const int* rel1 = rel_index + (size_t)(qt * 128 + r1) * KVL;

    // issue cp.async for K/V tile kt into buffer buf (raw fp32; HW tf32-truncates)
    auto kvissue = [&](int buf, int kt) {
        float* Kb = smem + buf * KVBUF;
        float* Vb = Kb + 2304;
#pragma unroll
        for (int i = 0; i < 2; i++) {
            int f = tid + i * 256;          // 0..511 : 64 rows x 8 float4
            int r = f >> 3, c4 = (f & 7) << 2;
            cpa16(&Kb[r * 36 + c4], &kbase[((size_t)(kt * 64) + r) * HDIM + c4]);
            cpa16(&Vb[r * 36 + c4], &vbase[((size_t)(kt * 64) + r) * HDIM + c4]);
        }
    };

    // ---- Q fragments (registers, rna-converted once) ----
    uint32_t qa[4][4];
    {
        const float* qbase = g_Q + (((size_t)(b * 8 + h) * QL) + qt * 128) * HDIM;
#pragma unroll
        for (int ks = 0; ks < 4; ks++) {
            qa[ks][0] = __float_as_uint(tf32r(qbase[(size_t)r0 * HDIM + ks * 8 + tig]));
            qa[ks][1] = __float_as_uint(tf32r(qbase[(size_t)r1 * HDIM + ks * 8 + tig]));
            qa[ks][2] = __float_as_uint(tf32r(qbase[(size_t)r0 * HDIM + ks * 8 + tig + 4]));
            qa[ks][3] = __float_as_uint(tf32r(qbase[(size_t)r1 * HDIM + ks * 8 + tig + 4]));
        }
    }

    float o[4][4];
#pragma unroll
    for (int i = 0; i < 4; i++)
#pragma unroll
        for (int j = 0; j < 4; j++) o[i][j] = 0.f;

    float m0 = -1e30f, m1 = -1e30f, l0 = 0.f, l1 = 0.f;

    kvissue(0, 0); cp_commit();

    for (int kt = 0; kt < KVL / 64; kt++) {
        __syncthreads();                 // everyone done reading the buffer being refilled
        if (kt < 63) { kvissue((kt + 1) & 1, kt + 1); cp_commit(); }
        if (kt < 63) cp_wait<1>(); else cp_wait<0>();
        __syncthreads();                 // tile kt visible to all warps

        const float* Ksm = smem + (kt & 1) * KVBUF;
        const float* Vsm = Ksm + 2304;

        // ---- S = Q K^T + bias ----
        float sA[8][4];
#pragma unroll
        for (int nt = 0; nt < 8; nt++) {
            const int cc = kt * 64 + nt * 8 + tig * 2;
            int2 ia = __ldg((const int2*)&rel0[cc]);
            int2 ib = __ldg((const int2*)&rel1[cc]);
            sA[nt][0] = __ldg(&bias_table[(size_t)ia.x * NHEADS + h]);
            sA[nt][1] = __ldg(&bias_table[(size_t)ia.y * NHEADS + h]);
            sA[nt][2] = __ldg(&bias_table[(size_t)ib.x * NHEADS + h]);
            sA[nt][3] = __ldg(&bias_table[(size_t)ib.y * NHEADS + h]);
#pragma unroll
            for (int ks = 0; ks < 4; ks++) {
                uint32_t b0 = __float_as_uint(Ksm[(nt * 8 + g) * 36 + ks * 8 + tig]);
                uint32_t b1 = __float_as_uint(Ksm[(nt * 8 + g) * 36 + ks * 8 + tig + 4]);
                mma_tf32(sA[nt], qa[ks][0], qa[ks][1], qa[ks][2], qa[ks][3], b0, b1);
            }
        }

        // ---- online softmax (register state; reduce over tig quad) ----
        float mloc0 = -1e30f, mloc1 = -1e30f;
#pragma unroll
        for (int nt = 0; nt < 8; nt++) {
            mloc0 = fmaxf(mloc0, fmaxf(sA[nt][0], sA[nt][1]));
            mloc1 = fmaxf(mloc1, fmaxf(sA[nt][2], sA[nt][3]));
        }
        mloc0 = fmaxf(mloc0, __shfl_xor_sync(0xffffffffu, mloc0, 1));
        mloc0 = fmaxf(mloc0, __shfl_xor_sync(0xffffffffu, mloc0, 2));
        mloc1 = fmaxf(mloc1, __shfl_xor_sync(0xffffffffu, mloc1, 1));
        mloc1 = fmaxf(mloc1, __shfl_xor_sync(0xffffffffu, mloc1, 2));

        float nm0 = fmaxf(m0, mloc0);
        float nm1 = fmaxf(m1, mloc1);
        float a0 = __expf(m0 - nm0);
        float a1 = __expf(m1 - nm1);
        m0 = nm0; m1 = nm1;

        float lsum0 = 0.f, lsum1 = 0.f;
#pragma unroll
        for (int nt = 0; nt < 8; nt++) {
            float p0 = __expf(sA[nt][0] - m0);
            float p1 = __expf(sA[nt][1] - m0);
            float p2 = __expf(sA[nt][2] - m1);
            float p3 = __expf(sA[nt][3] - m1);
            lsum0 += p0 + p1;
            lsum1 += p2 + p3;
            int cc = nt * 8 + tig * 2;
            float2 w0; w0.x = p0; w0.y = p1;
            float2 w1; w1.x = p2; w1.y = p3;
            *(float2*)&Psm[r0 * 68 + cc] = w0;
            *(float2*)&Psm[r1 * 68 + cc] = w1;
        }
        lsum0 += __shfl_xor_sync(0xffffffffu, lsum0, 1);
        lsum0 += __shfl_xor_sync(0xffffffffu, lsum0, 2);
        lsum1 += __shfl_xor_sync(0xffffffffu, lsum1, 1);
        lsum1 += __shfl_xor_sync(0xffffffffu, lsum1, 2);
        l0 = l0 * a0 + lsum0;
        l1 = l1 * a1 + lsum1;

#pragma unroll
        for (int nt2 = 0; nt2 < 4; nt2++) {
            o[nt2][0] *= a0; o[nt2][1] *= a0;
            o[nt2][2] *= a1; o[nt2][3] *= a1;
        }
        __syncwarp();  // P visible within warp (warp-local rows)

        // ---- O += P V ----
#pragma unroll
        for (int kc = 0; kc < 8; kc++) {
            uint32_t a0r = __float_as_uint(Psm[r0 * 68 + kc * 8 + tig]);
            uint32_t a1r = __float_as_uint(Psm[r1 * 68 + kc * 8 + tig]);
            uint32_t a2r = __float_as_uint(Psm[r0 * 68 + kc * 8 + tig + 4]);
            uint32_t a3r = __float_as_uint(Psm[r1 * 68 + kc * 8 + tig + 4]);
#pragma unroll
            for (int nt2 = 0; nt2 < 4; nt2++) {
                uint32_t b0 = __float_as_uint(Vsm[(kc * 8 + tig) * 36 + nt2 * 8 + g]);
                uint32_t b1 = __float_as_uint(Vsm[(kc * 8 + tig + 4) * 36 + nt2 * 8 + g]);
                mma_tf32(o[nt2], a0r, a1r, a2r, a3r, b0, b1);
            }
        }
        __syncwarp();  // PV reads done before next tile's P stores
    }

    // ---- epilogue: normalize + write to g_X ----
    float linv0 = 1.f / l0;
    float linv1 = 1.f / l1;
    float* xb = g_X + ((size_t)b * QL + qt * 128) * DIMC + h * HDIM;
#pragma unroll
    for (int nt2 = 0; nt2 < 4; nt2++) {
        int cc = nt2 * 8 + tig * 2;
        float2 v0; v0.x = o[nt2][0] * linv0; v0.y = o[nt2][1] * linv0;
        float2 v1; v1.x = o[nt2][2] * linv1; v1.y = o[nt2][3] * linv1;
        *(float2*)&xb[(size_t)r0 * DIMC + cc] = v0;
        *(float2*)&xb[(size_t)r1 * DIMC + cc] = v1;
    }
}

// ---------------- launch ----------------
extern "C" void kernel_launch(void* const* d_in, const int* in_sizes, int n_in,
                              void* d_out, int out_size)
{
    const float* q          = (const float*)d_in[0];
    const float* kv         = (const float*)d_in[1];
    const float* Wq         = (const float*)d_in[2];
    const float* bq         = (const float*)d_in[3];
    const float* Wkv        = (const float*)d_in[4];
    const float* bkv        = (const float*)d_in[5];
    const float* bias_table = (const float*)d_in[6];
    const float* Wp         = (const float*)d_in[7];
    const float* bp         = (const float*)d_in[8];
    const int*   rel_index  = (const int*)d_in[9];
    float* out = (float*)d_out;

    cudaFuncSetAttribute(gemm_tc<0>, cudaFuncAttributeMaxDynamicSharedMemorySize, GEMM_SMEM_BYTES);
    cudaFuncSetAttribute(gemm_tc<1>, cudaFuncAttributeMaxDynamicSharedMemorySize, GEMM_SMEM_BYTES);
    cudaFuncSetAttribute(gemm_tc<2>, cudaFuncAttributeMaxDynamicSharedMemorySize, GEMM_SMEM_BYTES);
    cudaFuncSetAttribute(attn_tc, cudaFuncAttributeMaxDynamicSharedMemorySize, ATTN_SMEM_BYTES);

    // Q projection: M=4096, N=256
    gemm_tc<0><<<dim3(32, 4), 256, GEMM_SMEM_BYTES>>>(q, Wq, bq, nullptr);
    // KV projection: M=16384, N=512
    gemm_tc<1><<<dim3(128, 8), 256, GEMM_SMEM_BYTES>>>(kv, Wkv, bkv, nullptr);
    // fused attention
    attn_tc<<<dim3(8, 8, 4), 256, ATTN_SMEM_BYTES>>>(bias_table, rel_index);
    // output projection: M=4096, N=256
    gemm_tc<2><<<dim3(32, 4), 256, GEMM_SMEM_BYTES>>>(nullptr, Wp, bp, out);
}